// round 8
// baseline (speedup 1.0000x reference)
#include <cuda_runtime.h>
#include <cuda_bf16.h>
#include <stdint.h>

// C[N=256, S=32768] = x[N,512] @ gather(W, ids)[S,512]^T + bias[ids]
// Legacy tensor path (toolchain targets sm_103 -> no tcgen05).
// fp32 accuracy via 3x bf16 split: x_hi*w_hi + x_lo*w_hi + x_hi*w_lo.
//
// Fused: BM=256 covers all of N, each CTA owns its 128 sample rows ->
// gather+convert W in-kernel. A (x) pre-split to bf16 [hi32|lo32] once,
// pipelined via 3-stage cp.async. B converted fp32->hi/lo bf16 in-loop,
// double-buffered. int32-vs-int64 ids detected per-CTA (no serial kernel).
//
// MMA schedule per chunk (24 ldsm4, 96 HMMA):
//   (a0,b0)(a0,b2)(a2,b0)(a1,b1)(a1,b3)(a3,b1)
//   hh: (a0,b0),(a1,b1)  hl: (a0,b2),(a1,b3)  lh: (a2,b0),(a3,b1)

#define BM 256
#define BN 128
#define NCH 16                      // K chunks: 512 / 32
#define A_STAGE 32768               // 256 rows x 128B
#define B_STAGE 16384               // 128 rows x 128B
#define OFF_B   (3 * A_STAGE)
#define OFF_BIAS (OFF_B + 2 * B_STAGE)
#define SMEM_TOTAL (OFF_BIAS + 512)

#define SWZ(o) ((o) ^ (((o) >> 3) & 0x70))

__device__ __nv_bfloat16 g_xa[256 * 1024];   // x split: [row][chunk][hi32|lo32]

__device__ __forceinline__ uint32_t smem_u32(const void* p) {
    uint32_t a;
    asm("{ .reg .u64 t; cvta.to.shared.u64 t, %1; cvt.u32.u64 %0, t; }" : "=r"(a) : "l"(p));
    return a;
}

__device__ __forceinline__ void cvt2(float f0, float f1, uint32_t& hi, uint32_t& lo) {
    __nv_bfloat162 h = __floats2bfloat162_rn(f0, f1);
    hi = *reinterpret_cast<uint32_t*>(&h);
    float r0 = f0 - __bfloat162float(__low2bfloat16(h));
    float r1 = f1 - __bfloat162float(__high2bfloat16(h));
    __nv_bfloat162 l = __floats2bfloat162_rn(r0, r1);
    lo = *reinterpret_cast<uint32_t*>(&l);
}

__device__ __forceinline__ uint4 ldsm4(uint32_t a) {
    uint4 r;
    asm volatile("ldmatrix.sync.aligned.m8n8.x4.shared.b16 {%0,%1,%2,%3}, [%4];"
                 : "=r"(r.x), "=r"(r.y), "=r"(r.z), "=r"(r.w) : "r"(a));
    return r;
}

#define CP16(dst, src) \
    asm volatile("cp.async.cg.shared.global [%0], [%1], 16;" :: "r"(dst), "l"(src))
#define CP_COMMIT() asm volatile("cp.async.commit_group;" ::: "memory")
#define CP_WAIT1()  asm volatile("cp.async.wait_group 1;" ::: "memory")

__device__ __forceinline__ void mma_bf16(float* c, const uint4& a, uint32_t b0, uint32_t b1) {
    asm volatile(
        "mma.sync.aligned.m16n8k16.row.col.f32.bf16.bf16.f32 "
        "{%0,%1,%2,%3}, {%4,%5,%6,%7}, {%8,%9}, {%0,%1,%2,%3};"
        : "+f"(c[0]), "+f"(c[1]), "+f"(c[2]), "+f"(c[3])
        : "r"(a.x), "r"(a.y), "r"(a.z), "r"(a.w), "r"(b0), "r"(b1));
}

// x -> g_xa. One block per row, thread = one float4.
__global__ void convert_x_kernel(const float* __restrict__ x, int D) {
    int row = blockIdx.x;
    int u = threadIdx.x;
    float4 v = reinterpret_cast<const float4*>(x + (size_t)row * D)[u];
    int chunk = u >> 3, wi = (u & 7) << 2;
    __nv_bfloat16* dst = g_xa + ((size_t)row << 10) + (chunk << 6) + wi;
    uint32_t h0, l0, h1, l1;
    cvt2(v.x, v.y, h0, l0);
    cvt2(v.z, v.w, h1, l1);
    uint32_t* ph = reinterpret_cast<uint32_t*>(dst);
    ph[0] = h0; ph[1] = h1;
    uint32_t* pl = reinterpret_cast<uint32_t*>(dst + 32);
    pl[0] = l0; pl[1] = l1;
}

__global__ __launch_bounds__(512, 1)
void lsh_gemm_kernel(const float* __restrict__ w, const float* __restrict__ bias,
                     const long long* __restrict__ ids, float* __restrict__ out,
                     int D, int S, int rows)
{
    extern __shared__ char smem[];
    uint32_t sb = smem_u32(smem);
    float* sbias = reinterpret_cast<float*>(smem + OFF_BIAS);
    __shared__ int sflag;

    const int tid = threadIdx.x, lane = tid & 31, wid = tid >> 5;
    const int s0 = blockIdx.x * BN;
    const int warp_m = wid & 3, warp_n = wid >> 2;

    // --- per-CTA ids dtype detection: the 64 int64-words covering this CTA's
    // 128 ids (if int32). int32 pairs misread as int64 are out of range
    // whenever the odd-position id != 0.
    if (tid == 0) sflag = 0;
    __syncthreads();
    if (tid < 64) {
        long long v = ids[(s0 >> 1) + tid];
        if (v < 0 || v >= (long long)rows) sflag = 1;
    }
    __syncthreads();
    const int ids32 = sflag;

    // --- W gather setup: row = tid/4 (0..127), part = tid%4, 8 floats each
    const int brow = tid >> 2;
    const int bpart = tid & 3;
    long long gid = ids32 ? (long long)(((const int*)ids)[s0 + brow])
                          : ids[s0 + brow];
    const float* wptr = w + gid * (long long)D + (bpart << 3);

    if (tid < BN) {
        long long g2 = ids32 ? (long long)(((const int*)ids)[s0 + tid])
                             : ids[s0 + tid];
        sbias[tid] = bias[g2];
    }

    // --- A cp.async coords: row = tid/2 (0..255), half = tid%2 (64B each)
    const int arow = tid >> 1, ahalf = tid & 1;
    const __nv_bfloat16* asrc = g_xa + ((size_t)arow << 10) + (ahalf << 5);
    const uint32_t adst = arow * 128 + (ahalf << 6);

    float acc[4][4][4];
    #pragma unroll
    for (int i = 0; i < 4; i++)
        #pragma unroll
        for (int j = 0; j < 4; j++)
            #pragma unroll
            for (int r = 0; r < 4; r++) acc[i][j][r] = 0.0f;

    // ldmatrix base offsets (bytes, pre-swizzle)
    const uint32_t a_rowb = ((warp_m << 6) + (lane & 15)) * 128 + (((uint32_t)lane >> 4) << 4);
    const uint32_t b_rowb = ((warp_n << 5) + (lane & 7) + (((uint32_t)lane >> 4) << 3)) * 128
                          + ((((uint32_t)lane >> 3) & 1) << 4);

    // B hi/lo smem byte offsets for this thread's 8 floats
    const uint32_t bst_hi = brow * 128 + (bpart << 4);
    const uint32_t bst_lo = bst_hi + 64;

    // prologue: A stages 0,1 + W chunk 0
    #pragma unroll
    for (int s = 0; s < 2; s++) {
        uint32_t base = sb + s * A_STAGE;
        #pragma unroll
        for (int j = 0; j < 4; j++)
            CP16(base + SWZ(adst + j * 16), asrc + s * 64 + j * 8);
        CP_COMMIT();
    }
    float4 wf0 = *reinterpret_cast<const float4*>(wptr);
    float4 wf1 = *reinterpret_cast<const float4*>(wptr + 4);

    for (int c = 0; c < NCH; ++c) {
        // prefetch next W chunk (consumed next iteration)
        float4 wn0, wn1;
        if (c + 1 < NCH) {
            wn0 = *reinterpret_cast<const float4*>(wptr + (c + 1) * 32);
            wn1 = *reinterpret_cast<const float4*>(wptr + (c + 1) * 32 + 4);
        }

        // convert + stage B chunk c into buf c&1
        {
            uint32_t bbase = sb + OFF_B + (c & 1) * B_STAGE;
            uint32_t h0, l0, h1, l1, h2, l2, h3, l3;
            cvt2(wf0.x, wf0.y, h0, l0);
            cvt2(wf0.z, wf0.w, h1, l1);
            cvt2(wf1.x, wf1.y, h2, l2);
            cvt2(wf1.z, wf1.w, h3, l3);
            asm volatile("st.shared.v4.b32 [%0], {%1,%2,%3,%4};"
                         :: "r"(bbase + SWZ(bst_hi)), "r"(h0), "r"(h1), "r"(h2), "r"(h3));
            asm volatile("st.shared.v4.b32 [%0], {%1,%2,%3,%4};"
                         :: "r"(bbase + SWZ(bst_lo)), "r"(l0), "r"(l1), "r"(l2), "r"(l3));
        }

        CP_WAIT1();
        __syncthreads();

        // issue A stage c+2 (its buffer was consumed in iter c-1)
        if (c + 2 < NCH) {
            uint32_t base = sb + ((c + 2) % 3) * A_STAGE;
            #pragma unroll
            for (int j = 0; j < 4; j++)
                CP16(base + SWZ(adst + j * 16), asrc + (c + 2) * 64 + j * 8);
        }
        CP_COMMIT();  // every iter (possibly empty) to keep wait accounting

        const uint32_t sA = sb + (c % 3) * A_STAGE;
        const uint32_t sB = sb + OFF_B + (c & 1) * B_STAGE;

        // schedule: (a0,b0)(a0,b2)(a2,b0)(a1,b1)(a1,b3)(a3,b1)
        // one live A set, two live B pairs; every fragment loaded once.
        uint4 af[4], bA0, bA1, bB0, bB1;
        #define LOAD_A(k) { _Pragma("unroll") \
            for (int im = 0; im < 4; ++im) \
                af[im] = ldsm4(sA + SWZ(a_rowb + im * 2048 + (k) * 32)); }
        #define MMA4(B0, B1) { _Pragma("unroll") \
            for (int im = 0; im < 4; ++im) { \
                mma_bf16(acc[im][0], af[im], B0.x, B0.y); \
                mma_bf16(acc[im][1], af[im], B0.z, B0.w); \
                mma_bf16(acc[im][2], af[im], B1.x, B1.y); \
                mma_bf16(acc[im][3], af[im], B1.z, B1.w); } }

        LOAD_A(0);                                     // a0
        bA0 = ldsm4(sB + SWZ(b_rowb + 0 * 32));        // b0
        bA1 = ldsm4(sB + SWZ(b_rowb + 2048 + 0 * 32));
        MMA4(bA0, bA1);                                // a0*b0 (hh k0)
        bB0 = ldsm4(sB + SWZ(b_rowb + 2 * 32));        // b2
        bB1 = ldsm4(sB + SWZ(b_rowb + 2048 + 2 * 32));
        MMA4(bB0, bB1);                                // a0*b2 (hl k0)
        LOAD_A(2);                                     // a2
        MMA4(bA0, bA1);                                // a2*b0 (lh k0)
        LOAD_A(1);                                     // a1
        bA0 = ldsm4(sB + SWZ(b_rowb + 1 * 32));        // b1
        bA1 = ldsm4(sB + SWZ(b_rowb + 2048 + 1 * 32));
        MMA4(bA0, bA1);                                // a1*b1 (hh k1)
        bB0 = ldsm4(sB + SWZ(b_rowb + 3 * 32));        // b3
        bB1 = ldsm4(sB + SWZ(b_rowb + 2048 + 3 * 32));
        MMA4(bB0, bB1);                                // a1*b3 (hl k1)
        LOAD_A(3);                                     // a3
        MMA4(bA0, bA1);                                // a3*b1 (lh k1)
        #undef LOAD_A
        #undef MMA4

        wf0 = wn0; wf1 = wn1;
    }

    // epilogue: bias + float2 stores
    #pragma unroll
    for (int im = 0; im < 4; ++im) {
        int r = (warp_m << 6) + (im << 4) + (lane >> 2);
        #pragma unroll
        for (int j = 0; j < 4; ++j) {
            int cl = (warp_n << 5) + (j << 3) + ((lane & 3) << 1);
            float b0 = sbias[cl], b1 = sbias[cl + 1];
            float2 v0 = make_float2(acc[im][j][0] + b0, acc[im][j][1] + b1);
            float2 v1 = make_float2(acc[im][j][2] + b0, acc[im][j][3] + b1);
            *reinterpret_cast<float2*>(out + (size_t)r * S + s0 + cl)       = v0;
            *reinterpret_cast<float2*>(out + (size_t)(r + 8) * S + s0 + cl) = v1;
        }
    }
}

extern "C" void kernel_launch(void* const* d_in, const int* in_sizes, int n_in,
                              void* d_out, int out_size)
{
    const float*     x    = (const float*)d_in[0];
    const float*     w    = (const float*)d_in[1];
    const float*     bias = (const float*)d_in[2];
    const long long* ids  = (const long long*)d_in[3];
    float*           out  = (float*)d_out;

    const int rows = in_sizes[2];            // NUM_CLASS + 1
    const int D    = in_sizes[1] / rows;     // 512
    const int N    = in_sizes[0] / D;        // 256
    const int S    = in_sizes[3];            // 32768

    cudaFuncSetAttribute(lsh_gemm_kernel,
                         cudaFuncAttributeMaxDynamicSharedMemorySize, SMEM_TOTAL);

    convert_x_kernel<<<N, 128>>>(x, D);
    lsh_gemm_kernel<<<S / BN, 512, SMEM_TOTAL>>>(w, bias, ids, out, D, S, rows);
}

// round 9
// speedup vs baseline: 1.0103x; 1.0103x over previous
#include <cuda_runtime.h>
#include <cuda_bf16.h>
#include <stdint.h>

// C[N=256, S=32768] = x[N,512] @ gather(W, ids)[S,512]^T + bias[ids]
// Legacy tensor path (toolchain targets sm_103 -> no tcgen05).
// fp32 accuracy via 3x bf16 split: x_hi*w_hi + x_lo*w_hi + x_hi*w_lo.
//
// Fused: BM=256 covers all of N, each CTA owns its 128 sample rows ->
// gather+convert W in-kernel. A (x) pre-split to bf16 [hi32|lo32] once,
// pipelined via 3-stage cp.async. B converted fp32->hi/lo bf16 in-loop,
// double-buffered. int32-vs-int64 ids detected per-CTA (no serial kernel).
//
// MMA schedule per chunk (24 ldsm4, 96 HMMA):
//   (a0,b0)(a0,b2)(a2,b0)(a1,b1)(a1,b3)(a3,b1)
//   hh: (a0,b0),(a1,b1)  hl: (a0,b2),(a1,b3)  lh: (a2,b0),(a3,b1)

#define BM 256
#define BN 128
#define NCH 16                      // K chunks: 512 / 32
#define A_STAGE 32768               // 256 rows x 128B
#define B_STAGE 16384               // 128 rows x 128B
#define OFF_B   (3 * A_STAGE)
#define OFF_BIAS (OFF_B + 2 * B_STAGE)
#define SMEM_TOTAL (OFF_BIAS + 512)

#define SWZ(o) ((o) ^ (((o) >> 3) & 0x70))

__device__ __nv_bfloat16 g_xa[256 * 1024];   // x split: [row][chunk][hi32|lo32]

__device__ __forceinline__ uint32_t smem_u32(const void* p) {
    uint32_t a;
    asm("{ .reg .u64 t; cvta.to.shared.u64 t, %1; cvt.u32.u64 %0, t; }" : "=r"(a) : "l"(p));
    return a;
}

__device__ __forceinline__ void cvt2(float f0, float f1, uint32_t& hi, uint32_t& lo) {
    __nv_bfloat162 h = __floats2bfloat162_rn(f0, f1);
    hi = *reinterpret_cast<uint32_t*>(&h);
    float r0 = f0 - __bfloat162float(__low2bfloat16(h));
    float r1 = f1 - __bfloat162float(__high2bfloat16(h));
    __nv_bfloat162 l = __floats2bfloat162_rn(r0, r1);
    lo = *reinterpret_cast<uint32_t*>(&l);
}

__device__ __forceinline__ uint4 ldsm4(uint32_t a) {
    uint4 r;
    asm volatile("ldmatrix.sync.aligned.m8n8.x4.shared.b16 {%0,%1,%2,%3}, [%4];"
                 : "=r"(r.x), "=r"(r.y), "=r"(r.z), "=r"(r.w) : "r"(a));
    return r;
}

#define CP16(dst, src) \
    asm volatile("cp.async.cg.shared.global [%0], [%1], 16;" :: "r"(dst), "l"(src))
#define CP_COMMIT() asm volatile("cp.async.commit_group;" ::: "memory")
#define CP_WAIT1()  asm volatile("cp.async.wait_group 1;" ::: "memory")

__device__ __forceinline__ void mma_bf16(float* c, const uint4& a, uint32_t b0, uint32_t b1) {
    asm volatile(
        "mma.sync.aligned.m16n8k16.row.col.f32.bf16.bf16.f32 "
        "{%0,%1,%2,%3}, {%4,%5,%6,%7}, {%8,%9}, {%0,%1,%2,%3};"
        : "+f"(c[0]), "+f"(c[1]), "+f"(c[2]), "+f"(c[3])
        : "r"(a.x), "r"(a.y), "r"(a.z), "r"(a.w), "r"(b0), "r"(b1));
}

// x -> g_xa. One block per row, thread = one float4.
__global__ void convert_x_kernel(const float* __restrict__ x, int D) {
    int row = blockIdx.x;
    int u = threadIdx.x;
    float4 v = reinterpret_cast<const float4*>(x + (size_t)row * D)[u];
    int chunk = u >> 3, wi = (u & 7) << 2;
    __nv_bfloat16* dst = g_xa + ((size_t)row << 10) + (chunk << 6) + wi;
    uint32_t h0, l0, h1, l1;
    cvt2(v.x, v.y, h0, l0);
    cvt2(v.z, v.w, h1, l1);
    uint32_t* ph = reinterpret_cast<uint32_t*>(dst);
    ph[0] = h0; ph[1] = h1;
    uint32_t* pl = reinterpret_cast<uint32_t*>(dst + 32);
    pl[0] = l0; pl[1] = l1;
}

__global__ __launch_bounds__(512, 1)
void lsh_gemm_kernel(const float* __restrict__ w, const float* __restrict__ bias,
                     const long long* __restrict__ ids, float* __restrict__ out,
                     int D, int S, int rows)
{
    extern __shared__ char smem[];
    uint32_t sb = smem_u32(smem);
    float* sbias = reinterpret_cast<float*>(smem + OFF_BIAS);
    __shared__ int sflag;

    const int tid = threadIdx.x, lane = tid & 31, wid = tid >> 5;
    const int s0 = blockIdx.x * BN;
    const int warp_m = wid & 3, warp_n = wid >> 2;

    // --- per-CTA ids dtype detection: the 64 int64-words covering this CTA's
    // 128 ids (if int32). int32 pairs misread as int64 are out of range
    // whenever the odd-position id != 0.
    if (tid == 0) sflag = 0;
    __syncthreads();
    if (tid < 64) {
        long long v = ids[(s0 >> 1) + tid];
        if (v < 0 || v >= (long long)rows) sflag = 1;
    }
    __syncthreads();
    const int ids32 = sflag;

    // --- W gather setup: row = tid/4 (0..127), part = tid%4, 8 floats each
    const int brow = tid >> 2;
    const int bpart = tid & 3;
    long long gid = ids32 ? (long long)(((const int*)ids)[s0 + brow])
                          : ids[s0 + brow];
    const float* wptr = w + gid * (long long)D + (bpart << 3);

    if (tid < BN) {
        long long g2 = ids32 ? (long long)(((const int*)ids)[s0 + tid])
                             : ids[s0 + tid];
        sbias[tid] = bias[g2];
    }

    // --- A cp.async coords: row = tid/2 (0..255), half = tid%2 (64B each)
    const int arow = tid >> 1, ahalf = tid & 1;
    const __nv_bfloat16* asrc = g_xa + ((size_t)arow << 10) + (ahalf << 5);
    const uint32_t adst = arow * 128 + (ahalf << 6);

    float acc[4][4][4];
    #pragma unroll
    for (int i = 0; i < 4; i++)
        #pragma unroll
        for (int j = 0; j < 4; j++)
            #pragma unroll
            for (int r = 0; r < 4; r++) acc[i][j][r] = 0.0f;

    // ldmatrix base offsets (bytes, pre-swizzle)
    const uint32_t a_rowb = ((warp_m << 6) + (lane & 15)) * 128 + (((uint32_t)lane >> 4) << 4);
    const uint32_t b_rowb = ((warp_n << 5) + (lane & 7) + (((uint32_t)lane >> 4) << 3)) * 128
                          + ((((uint32_t)lane >> 3) & 1) << 4);

    // B hi/lo smem byte offsets for this thread's 8 floats
    const uint32_t bst_hi = brow * 128 + (bpart << 4);
    const uint32_t bst_lo = bst_hi + 64;

    // prologue: A stages 0,1 + W chunk 0
    #pragma unroll
    for (int s = 0; s < 2; s++) {
        uint32_t base = sb + s * A_STAGE;
        #pragma unroll
        for (int j = 0; j < 4; j++)
            CP16(base + SWZ(adst + j * 16), asrc + s * 64 + j * 8);
        CP_COMMIT();
    }
    float4 wf0 = *reinterpret_cast<const float4*>(wptr);
    float4 wf1 = *reinterpret_cast<const float4*>(wptr + 4);

    for (int c = 0; c < NCH; ++c) {
        // prefetch next W chunk (consumed next iteration)
        float4 wn0, wn1;
        if (c + 1 < NCH) {
            wn0 = *reinterpret_cast<const float4*>(wptr + (c + 1) * 32);
            wn1 = *reinterpret_cast<const float4*>(wptr + (c + 1) * 32 + 4);
        }

        // convert + stage B chunk c into buf c&1
        {
            uint32_t bbase = sb + OFF_B + (c & 1) * B_STAGE;
            uint32_t h0, l0, h1, l1, h2, l2, h3, l3;
            cvt2(wf0.x, wf0.y, h0, l0);
            cvt2(wf0.z, wf0.w, h1, l1);
            cvt2(wf1.x, wf1.y, h2, l2);
            cvt2(wf1.z, wf1.w, h3, l3);
            asm volatile("st.shared.v4.b32 [%0], {%1,%2,%3,%4};"
                         :: "r"(bbase + SWZ(bst_hi)), "r"(h0), "r"(h1), "r"(h2), "r"(h3));
            asm volatile("st.shared.v4.b32 [%0], {%1,%2,%3,%4};"
                         :: "r"(bbase + SWZ(bst_lo)), "r"(l0), "r"(l1), "r"(l2), "r"(l3));
        }

        CP_WAIT1();
        __syncthreads();

        // issue A stage c+2 (its buffer was consumed in iter c-1)
        if (c + 2 < NCH) {
            uint32_t base = sb + ((c + 2) % 3) * A_STAGE;
            #pragma unroll
            for (int j = 0; j < 4; j++)
                CP16(base + SWZ(adst + j * 16), asrc + (c + 2) * 64 + j * 8);
        }
        CP_COMMIT();  // every iter (possibly empty) to keep wait accounting

        const uint32_t sA = sb + (c % 3) * A_STAGE;
        const uint32_t sB = sb + OFF_B + (c & 1) * B_STAGE;

        // schedule: (a0,b0)(a0,b2)(a2,b0)(a1,b1)(a1,b3)(a3,b1)
        // one live A set, two live B pairs; every fragment loaded once.
        uint4 af[4], bA0, bA1, bB0, bB1;
        #define LOAD_A(k) { _Pragma("unroll") \
            for (int im = 0; im < 4; ++im) \
                af[im] = ldsm4(sA + SWZ(a_rowb + im * 2048 + (k) * 32)); }
        #define MMA4(B0, B1) { _Pragma("unroll") \
            for (int im = 0; im < 4; ++im) { \
                mma_bf16(acc[im][0], af[im], B0.x, B0.y); \
                mma_bf16(acc[im][1], af[im], B0.z, B0.w); \
                mma_bf16(acc[im][2], af[im], B1.x, B1.y); \
                mma_bf16(acc[im][3], af[im], B1.z, B1.w); } }

        LOAD_A(0);                                     // a0
        bA0 = ldsm4(sB + SWZ(b_rowb + 0 * 32));        // b0
        bA1 = ldsm4(sB + SWZ(b_rowb + 2048 + 0 * 32));
        MMA4(bA0, bA1);                                // a0*b0 (hh k0)
        bB0 = ldsm4(sB + SWZ(b_rowb + 2 * 32));        // b2
        bB1 = ldsm4(sB + SWZ(b_rowb + 2048 + 2 * 32));
        MMA4(bB0, bB1);                                // a0*b2 (hl k0)
        LOAD_A(2);                                     // a2
        MMA4(bA0, bA1);                                // a2*b0 (lh k0)
        LOAD_A(1);                                     // a1
        bA0 = ldsm4(sB + SWZ(b_rowb + 1 * 32));        // b1
        bA1 = ldsm4(sB + SWZ(b_rowb + 2048 + 1 * 32));
        MMA4(bA0, bA1);                                // a1*b1 (hh k1)
        bB0 = ldsm4(sB + SWZ(b_rowb + 3 * 32));        // b3
        bB1 = ldsm4(sB + SWZ(b_rowb + 2048 + 3 * 32));
        MMA4(bB0, bB1);                                // a1*b3 (hl k1)
        LOAD_A(3);                                     // a3
        MMA4(bA0, bA1);                                // a3*b1 (lh k1)
        #undef LOAD_A
        #undef MMA4

        wf0 = wn0; wf1 = wn1;
    }

    // epilogue: bias + float2 stores
    #pragma unroll
    for (int im = 0; im < 4; ++im) {
        int r = (warp_m << 6) + (im << 4) + (lane >> 2);
        #pragma unroll
        for (int j = 0; j < 4; ++j) {
            int cl = (warp_n << 5) + (j << 3) + ((lane & 3) << 1);
            float b0 = sbias[cl], b1 = sbias[cl + 1];
            float2 v0 = make_float2(acc[im][j][0] + b0, acc[im][j][1] + b1);
            float2 v1 = make_float2(acc[im][j][2] + b0, acc[im][j][3] + b1);
            *reinterpret_cast<float2*>(out + (size_t)r * S + s0 + cl)       = v0;
            *reinterpret_cast<float2*>(out + (size_t)(r + 8) * S + s0 + cl) = v1;
        }
    }
}

extern "C" void kernel_launch(void* const* d_in, const int* in_sizes, int n_in,
                              void* d_out, int out_size)
{
    const float*     x    = (const float*)d_in[0];
    const float*     w    = (const float*)d_in[1];
    const float*     bias = (const float*)d_in[2];
    const long long* ids  = (const long long*)d_in[3];
    float*           out  = (float*)d_out;

    const int rows = in_sizes[2];            // NUM_CLASS + 1
    const int D    = in_sizes[1] / rows;     // 512
    const int N    = in_sizes[0] / D;        // 256
    const int S    = in_sizes[3];            // 32768

    cudaFuncSetAttribute(lsh_gemm_kernel,
                         cudaFuncAttributeMaxDynamicSharedMemorySize, SMEM_TOTAL);

    convert_x_kernel<<<N, 128>>>(x, D);
    lsh_gemm_kernel<<<S / BN, 512, SMEM_TOTAL>>>(w, bias, ids, out, D, S, rows);
}